// round 7
// baseline (speedup 1.0000x reference)
#include <cuda_runtime.h>

// Shapes (fixed for this problem instance)
#define TOKENS 4096   // B*S = 2*2048
#define DDIM   1024   // D
#define WDIM   4096   // W
#define SLOT   8
#define CDIM   11
#define LEAVES 8      // 1 << TREE_DEPTH

// -------- scratch (device globals; no runtime allocation allowed) --------
__device__ float g_selp[WDIM * LEAVES * 12];   // [w][l][0..7]=slot weights, [8]=const bias (sel10-sel8)
__device__ float g_basis[TOKENS * 12];         // [t][0..7] = tanh slots (consts folded into g_selp bias)
__device__ float g_roots[(size_t)TOKENS * WDIM]; // 64MB fp32 roots

// ---------------- helpers ----------------
__device__ __forceinline__ float tanh_exp(float x) {
    // accurate-enough tanh (~1e-6 abs): 1 EX2 + 1 RCP on MUFU
    x = fminf(fmaxf(x, -15.0f), 15.0f);
    float t = __expf(2.0f * x);
    return __fdividef(t - 1.0f, t + 1.0f);
}

__device__ __forceinline__ unsigned long long pack2(float x, float y) {
    unsigned long long r;
    asm("mov.b64 %0, {%1, %2};" : "=l"(r) : "f"(x), "f"(y));
    return r;
}
__device__ __forceinline__ void unpack2(unsigned long long v, float &x, float &y) {
    asm("mov.b64 {%0, %1}, %2;" : "=f"(x), "=f"(y) : "l"(v));
}
// Blackwell packed fp32 FMA (2 lanes per reg-pair) — 2x FFMA throughput, PTX-only
__device__ __forceinline__ unsigned long long ffma2(unsigned long long a,
                                                    unsigned long long b,
                                                    unsigned long long c) {
    unsigned long long d;
    asm("fma.rn.f32x2 %0, %1, %2, %3;" : "=l"(d) : "l"(a), "l"(b), "l"(c));
    return d;
}

// ================= K1: selector softmax + constant folding =================
// one thread per (w,l) row of 11 logits
__global__ void k_selector(const float* __restrict__ logits) {
    int idx = blockIdx.x * blockDim.x + threadIdx.x;
    if (idx >= WDIM * LEAVES) return;
    const float* row = logits + (size_t)idx * CDIM;
    float v[CDIM];
    float m = -1e30f;
#pragma unroll
    for (int c = 0; c < CDIM; ++c) { v[c] = row[c]; m = fmaxf(m, v[c]); }
    float s = 0.0f;
#pragma unroll
    for (int c = 0; c < CDIM; ++c) { v[c] = __expf(v[c] - m); s += v[c]; }
    float inv = 1.0f / s;
    float* o = g_selp + (size_t)idx * 12;
#pragma unroll
    for (int c = 0; c < SLOT; ++c) o[c] = v[c] * inv;
    // constants contribution: (-1)*sel[8] + 0*sel[9] + 1*sel[10]
    o[8]  = (v[10] - v[8]) * inv;
    o[9]  = 0.0f; o[10] = 0.0f; o[11] = 0.0f;
}

// ================= K2: slots = tanh(hidden @ slot_w + b) =================
// one block (128 threads) per token
__global__ void k_basis(const float* __restrict__ hidden,
                        const float* __restrict__ slot_w,
                        const float* __restrict__ slot_b) {
    __shared__ float red[SLOT][128];
    const int t = blockIdx.x;
    const int tid = threadIdx.x;
    float acc[SLOT];
#pragma unroll
    for (int k = 0; k < SLOT; ++k) acc[k] = 0.0f;
    const float* h = hidden + (size_t)t * DDIM;
    for (int d = tid; d < DDIM; d += 128) {
        float hv = h[d];
        const float4* wr = (const float4*)(slot_w + (size_t)d * SLOT);
        float4 w0 = wr[0], w1 = wr[1];
        acc[0] = fmaf(hv, w0.x, acc[0]); acc[1] = fmaf(hv, w0.y, acc[1]);
        acc[2] = fmaf(hv, w0.z, acc[2]); acc[3] = fmaf(hv, w0.w, acc[3]);
        acc[4] = fmaf(hv, w1.x, acc[4]); acc[5] = fmaf(hv, w1.y, acc[5]);
        acc[6] = fmaf(hv, w1.z, acc[6]); acc[7] = fmaf(hv, w1.w, acc[7]);
    }
#pragma unroll
    for (int k = 0; k < SLOT; ++k) red[k][tid] = acc[k];
    __syncthreads();
    for (int off = 64; off > 0; off >>= 1) {
        if (tid < off) {
#pragma unroll
            for (int k = 0; k < SLOT; ++k) red[k][tid] += red[k][tid + off];
        }
        __syncthreads();
    }
    if (tid < SLOT) {
        g_basis[(size_t)t * 12 + tid] = tanhf(red[tid][0] + slot_b[tid]);
    } else if (tid < 12) {
        g_basis[(size_t)t * 12 + tid] = 0.0f;  // unused slots (consts folded into bias)
    }
}

// ================= K3: fused einsum + tree -> roots =================
#define TT 16
#define TW 16
#define SEL_WS 100   // padded per-w stride in smem (bank-friendly)

__device__ __forceinline__ float node_f(float L, float R,
                                        float c1, float c2, float pw, float nb) {
    float a = fmaf(pw * L, R, nb);
    a = fmaf(c2, R, a);
    a = fmaf(c1, L, a);
    return tanh_exp(a);
}

__global__ __launch_bounds__(256) void k_tree(const float* __restrict__ node_params) {
    __shared__ float s_sel[TW * SEL_WS];
    __shared__ float s_basis[TT * 12];
    __shared__ float s_out[TT * (TW + 1)];
    const int tid = threadIdx.x;
    const int tbase = blockIdx.x * TT;
    const int wbase = blockIdx.y * TW;

    for (int i = tid; i < TW * 96; i += 256) {
        int wi = i / 96, off = i - wi * 96;
        s_sel[wi * SEL_WS + off] = g_selp[(size_t)(wbase + wi) * 96 + off];
    }
    if (tid < TT * 12) s_basis[tid] = g_basis[(size_t)tbase * 12 + tid];
    __syncthreads();

    const int tloc = tid & 15;      // token (fast) -> sel reads broadcast in warp
    const int wloc = tid >> 4;      // w

    float bs[SLOT];
#pragma unroll
    for (int c = 0; c < SLOT; ++c) bs[c] = s_basis[tloc * 12 + c];

    const float* sp = s_sel + wloc * SEL_WS;
    float v[LEAVES];
#pragma unroll
    for (int l = 0; l < LEAVES; ++l) {
        const float4* q = (const float4*)(sp + l * 12);
        float4 w0 = q[0], w1 = q[1];
        float a = sp[l * 12 + 8];   // constants contribution
        a = fmaf(w0.x, bs[0], a); a = fmaf(w0.y, bs[1], a);
        a = fmaf(w0.z, bs[2], a); a = fmaf(w0.w, bs[3], a);
        a = fmaf(w1.x, bs[4], a); a = fmaf(w1.y, bs[5], a);
        a = fmaf(w1.z, bs[6], a); a = fmaf(w1.w, bs[7], a);
        v[l] = a;
    }

    const float lw = node_params[0], rw = node_params[1], pw = node_params[2];
    const float dw = node_params[3], nb = node_params[4];
    const float c1 = lw + dw, c2 = rw - dw;

    float n0 = node_f(v[0], v[1], c1, c2, pw, nb);
    float n1 = node_f(v[2], v[3], c1, c2, pw, nb);
    float n2 = node_f(v[4], v[5], c1, c2, pw, nb);
    float n3 = node_f(v[6], v[7], c1, c2, pw, nb);
    float m0 = node_f(n0, n1, c1, c2, pw, nb);
    float m1 = node_f(n2, n3, c1, c2, pw, nb);
    float root = node_f(m0, m1, c1, c2, pw, nb);

    s_out[tloc * (TW + 1) + wloc] = root;
    __syncthreads();
    // coalesced write: lanes -> consecutive w
    const int t2 = tid >> 4, w2 = tid & 15;
    g_roots[(size_t)(tbase + t2) * WDIM + wbase + w2] = s_out[t2 * (TW + 1) + w2];
}

// ================= K4: out = roots @ out_w + out_b (fp32, packed f32x2) ===
#define BM 128
#define BN 128
#define BK 16
#define AST (BM + 4)   // 132-float row stride for transposed A tile

__global__ __launch_bounds__(256, 2) void k_gemm(const float* __restrict__ Bw,
                                                 const float* __restrict__ bias,
                                                 float* __restrict__ C) {
    __shared__ float As[2][BK][AST];
    __shared__ float Bs[2][BK][BN];
    const int tid = threadIdx.x;
    const int bm = blockIdx.y * BM;
    const int bn = blockIdx.x * BN;
    const int K = WDIM;
    const float* A = g_roots;

    // global-load thread mapping
    const int aRow = tid >> 2;      // 0..63 (+64 for second)
    const int aQ   = tid & 3;       // quad within 16-float k-strip
    const int bRow = tid >> 5;      // 0..7 (+8)
    const int bQ   = tid & 31;      // quad within 128-float row

    float4 ra0, ra1, rb0, rb1;

#define GLOAD(kt)                                                                 \
    {                                                                             \
        const float* Ab = A + (size_t)(bm + aRow) * K + (kt) + aQ * 4;            \
        ra0 = *(const float4*)Ab;                                                 \
        ra1 = *(const float4*)(Ab + (size_t)64 * K);                              \
        const float* Bb = Bw + (size_t)((kt) + bRow) * DDIM + bn + bQ * 4;        \
        rb0 = *(const float4*)Bb;                                                 \
        rb1 = *(const float4*)(Bb + (size_t)8 * DDIM);                            \
    }

#define SSTORE(buf)                                                               \
    {                                                                             \
        As[buf][aQ * 4 + 0][aRow] = ra0.x; As[buf][aQ * 4 + 1][aRow] = ra0.y;     \
        As[buf][aQ * 4 + 2][aRow] = ra0.z; As[buf][aQ * 4 + 3][aRow] = ra0.w;     \
        As[buf][aQ * 4 + 0][aRow + 64] = ra1.x;                                   \
        As[buf][aQ * 4 + 1][aRow + 64] = ra1.y;                                   \
        As[buf][aQ * 4 + 2][aRow + 64] = ra1.z;                                   \
        As[buf][aQ * 4 + 3][aRow + 64] = ra1.w;                                   \
        *(float4*)&Bs[buf][bRow][bQ * 4]     = rb0;                               \
        *(float4*)&Bs[buf][bRow + 8][bQ * 4] = rb1;                               \
    }

    unsigned long long acc[8][4];
#pragma unroll
    for (int i = 0; i < 8; ++i)
#pragma unroll
        for (int j = 0; j < 4; ++j) acc[i][j] = 0ULL;

    const int ty = tid >> 4, tx = tid & 15;

    GLOAD(0);
    SSTORE(0);
    __syncthreads();

    const int NT = K / BK;   // 256
#pragma unroll 1
    for (int t = 0; t < NT; ++t) {
        const int cur = t & 1;
        if (t + 1 < NT) GLOAD((t + 1) * BK);
#pragma unroll
        for (int kk = 0; kk < BK; ++kk) {
            float4 a0 = *(const float4*)&As[cur][kk][ty * 8];
            float4 a1 = *(const float4*)&As[cur][kk][ty * 8 + 4];
            const ulonglong2* bqp = (const ulonglong2*)&Bs[cur][kk][tx * 8];
            ulonglong2 bp0 = bqp[0], bp1 = bqp[1];
            unsigned long long b0 = bp0.x, b1 = bp0.y, b2 = bp1.x, b3 = bp1.y;
            float av[8] = {a0.x, a0.y, a0.z, a0.w, a1.x, a1.y, a1.z, a1.w};
#pragma unroll
            for (int i = 0; i < 8; ++i) {
                unsigned long long a2 = pack2(av[i], av[i]);
                acc[i][0] = ffma2(a2, b0, acc[i][0]);
                acc[i][1] = ffma2(a2, b1, acc[i][1]);
                acc[i][2] = ffma2(a2, b2, acc[i][2]);
                acc[i][3] = ffma2(a2, b3, acc[i][3]);
            }
        }
        if (t + 1 < NT) {
            SSTORE(1 - cur);
            __syncthreads();
        }
    }

    // epilogue: add bias, store
    float br[8];
    *(float4*)&br[0] = *(const float4*)(bias + bn + tx * 8);
    *(float4*)&br[4] = *(const float4*)(bias + bn + tx * 8 + 4);
#pragma unroll
    for (int i = 0; i < 8; ++i) {
        float o[8];
        unpack2(acc[i][0], o[0], o[1]);
        unpack2(acc[i][1], o[2], o[3]);
        unpack2(acc[i][2], o[4], o[5]);
        unpack2(acc[i][3], o[6], o[7]);
        float4 s0, s1;
        s0.x = o[0] + br[0]; s0.y = o[1] + br[1]; s0.z = o[2] + br[2]; s0.w = o[3] + br[3];
        s1.x = o[4] + br[4]; s1.y = o[5] + br[5]; s1.z = o[6] + br[6]; s1.w = o[7] + br[7];
        float* crow = C + (size_t)(bm + ty * 8 + i) * DDIM + bn + tx * 8;
        *(float4*)crow = s0;
        *(float4*)(crow + 4) = s1;
    }
}

// ================= launch =================
extern "C" void kernel_launch(void* const* d_in, const int* in_sizes, int n_in,
                              void* d_out, int out_size) {
    const float* hidden      = (const float*)d_in[0];
    const float* slot_w      = (const float*)d_in[1];
    const float* slot_b      = (const float*)d_in[2];
    const float* leaf_logits = (const float*)d_in[3];
    const float* node_params = (const float*)d_in[4];
    const float* out_w       = (const float*)d_in[5];
    const float* out_b       = (const float*)d_in[6];
    float* out = (float*)d_out;
    (void)in_sizes; (void)n_in; (void)out_size;

    k_selector<<<(WDIM * LEAVES + 255) / 256, 256>>>(leaf_logits);
    k_basis<<<TOKENS, 128>>>(hidden, slot_w, slot_b);
    k_tree<<<dim3(TOKENS / TT, WDIM / TW), 256>>>(node_params);
    k_gemm<<<dim3(DDIM / BN, TOKENS / BM), 256>>>(out_w, out_b, out);
}

// round 13
// speedup vs baseline: 1.6685x; 1.6685x over previous
#include <cuda_runtime.h>
#include <cuda_bf16.h>
#include <cstdint>

// Shapes (fixed for this problem instance)
#define TOKENS 4096   // B*S = 2*2048
#define DDIM   1024   // D
#define WDIM   4096   // W
#define SLOT   8
#define CDIM   11
#define LEAVES 8      // 1 << TREE_DEPTH

// -------- scratch (device globals; no runtime allocation allowed) --------
__device__ float g_selp[WDIM * LEAVES * 12];   // [w][l][0..7]=slot weights, [8]=const bias
__device__ float g_basis[TOKENS * 12];         // [t][0..7] = tanh slots
__device__ __align__(256) __nv_bfloat16 g_Ah[(size_t)TOKENS * WDIM]; // roots hi
__device__ __align__(256) __nv_bfloat16 g_Al[(size_t)TOKENS * WDIM]; // roots lo
__device__ __align__(256) __nv_bfloat16 g_Bh[(size_t)WDIM * DDIM];   // out_w hi
__device__ __align__(256) __nv_bfloat16 g_Bl[(size_t)WDIM * DDIM];   // out_w lo

// ---------------- helpers ----------------
__device__ __forceinline__ float tanh_exp(float x) {
    x = fminf(fmaxf(x, -15.0f), 15.0f);
    float t = __expf(2.0f * x);
    return __fdividef(t - 1.0f, t + 1.0f);
}

__device__ __forceinline__ unsigned pb2(__nv_bfloat16 a, __nv_bfloat16 b) {
    unsigned short ua = __bfloat16_as_ushort(a), ub = __bfloat16_as_ushort(b);
    return (unsigned)ua | ((unsigned)ub << 16);
}

// ================= K1: selector softmax + constant folding =================
__global__ void k_selector(const float* __restrict__ logits) {
    int idx = blockIdx.x * blockDim.x + threadIdx.x;
    if (idx >= WDIM * LEAVES) return;
    const float* row = logits + (size_t)idx * CDIM;
    float v[CDIM];
    float m = -1e30f;
#pragma unroll
    for (int c = 0; c < CDIM; ++c) { v[c] = row[c]; m = fmaxf(m, v[c]); }
    float s = 0.0f;
#pragma unroll
    for (int c = 0; c < CDIM; ++c) { v[c] = __expf(v[c] - m); s += v[c]; }
    float inv = 1.0f / s;
    float* o = g_selp + (size_t)idx * 12;
#pragma unroll
    for (int c = 0; c < SLOT; ++c) o[c] = v[c] * inv;
    o[8]  = (v[10] - v[8]) * inv;   // (-1)*sel[8] + 1*sel[10]
    o[9]  = 0.0f; o[10] = 0.0f; o[11] = 0.0f;
}

// ================= K2: slots = tanh(hidden @ slot_w + b) =================
__global__ void k_basis(const float* __restrict__ hidden,
                        const float* __restrict__ slot_w,
                        const float* __restrict__ slot_b) {
    __shared__ float red[SLOT][128];
    const int t = blockIdx.x;
    const int tid = threadIdx.x;
    float acc[SLOT];
#pragma unroll
    for (int k = 0; k < SLOT; ++k) acc[k] = 0.0f;
    const float* h = hidden + (size_t)t * DDIM;
    for (int d = tid; d < DDIM; d += 128) {
        float hv = h[d];
        const float4* wr = (const float4*)(slot_w + (size_t)d * SLOT);
        float4 w0 = wr[0], w1 = wr[1];
        acc[0] = fmaf(hv, w0.x, acc[0]); acc[1] = fmaf(hv, w0.y, acc[1]);
        acc[2] = fmaf(hv, w0.z, acc[2]); acc[3] = fmaf(hv, w0.w, acc[3]);
        acc[4] = fmaf(hv, w1.x, acc[4]); acc[5] = fmaf(hv, w1.y, acc[5]);
        acc[6] = fmaf(hv, w1.z, acc[6]); acc[7] = fmaf(hv, w1.w, acc[7]);
    }
#pragma unroll
    for (int k = 0; k < SLOT; ++k) red[k][tid] = acc[k];
    __syncthreads();
    for (int off = 64; off > 0; off >>= 1) {
        if (tid < off) {
#pragma unroll
            for (int k = 0; k < SLOT; ++k) red[k][tid] += red[k][tid + off];
        }
        __syncthreads();
    }
    if (tid < SLOT) {
        g_basis[(size_t)t * 12 + tid] = tanhf(red[tid][0] + slot_b[tid]);
    } else if (tid < 12) {
        g_basis[(size_t)t * 12 + tid] = 0.0f;
    }
}

// ================= K2b: split out_w into bf16 hi/lo =================
__global__ void k_split(const float* __restrict__ w) {
    int i = blockIdx.x * 256 + threadIdx.x;     // i indexes float4 groups
    float4 v = ((const float4*)w)[i];
    float f[4] = {v.x, v.y, v.z, v.w};
    __nv_bfloat16 h[4], l[4];
#pragma unroll
    for (int j = 0; j < 4; ++j) {
        h[j] = __float2bfloat16(f[j]);
        l[j] = __float2bfloat16(f[j] - __bfloat162float(h[j]));
    }
    uint2 ph, pl;
    ph.x = pb2(h[0], h[1]); ph.y = pb2(h[2], h[3]);
    pl.x = pb2(l[0], l[1]); pl.y = pb2(l[2], l[3]);
    ((uint2*)g_Bh)[i] = ph;
    ((uint2*)g_Bl)[i] = pl;
}

// ================= K3: fused einsum + tree -> roots (bf16 hi/lo) ========
#define TT 16
#define TW 16
#define SEL_WS 100

__device__ __forceinline__ float node_f(float L, float R,
                                        float c1, float c2, float pw, float nb) {
    float a = fmaf(pw * L, R, nb);
    a = fmaf(c2, R, a);
    a = fmaf(c1, L, a);
    return tanh_exp(a);
}

__global__ __launch_bounds__(256) void k_tree(const float* __restrict__ node_params) {
    __shared__ float s_sel[TW * SEL_WS];
    __shared__ float s_basis[TT * 12];
    __shared__ float s_out[TT * (TW + 1)];
    const int tid = threadIdx.x;
    const int tbase = blockIdx.x * TT;
    const int wbase = blockIdx.y * TW;

    for (int i = tid; i < TW * 96; i += 256) {
        int wi = i / 96, off = i - wi * 96;
        s_sel[wi * SEL_WS + off] = g_selp[(size_t)(wbase + wi) * 96 + off];
    }
    if (tid < TT * 12) s_basis[tid] = g_basis[(size_t)tbase * 12 + tid];
    __syncthreads();

    const int tloc = tid & 15;
    const int wloc = tid >> 4;

    float bs[SLOT];
#pragma unroll
    for (int c = 0; c < SLOT; ++c) bs[c] = s_basis[tloc * 12 + c];

    const float* sp = s_sel + wloc * SEL_WS;
    float v[LEAVES];
#pragma unroll
    for (int l = 0; l < LEAVES; ++l) {
        const float4* q = (const float4*)(sp + l * 12);
        float4 w0 = q[0], w1 = q[1];
        float a = sp[l * 12 + 8];
        a = fmaf(w0.x, bs[0], a); a = fmaf(w0.y, bs[1], a);
        a = fmaf(w0.z, bs[2], a); a = fmaf(w0.w, bs[3], a);
        a = fmaf(w1.x, bs[4], a); a = fmaf(w1.y, bs[5], a);
        a = fmaf(w1.z, bs[6], a); a = fmaf(w1.w, bs[7], a);
        v[l] = a;
    }

    const float lw = node_params[0], rw = node_params[1], pw = node_params[2];
    const float dw = node_params[3], nb = node_params[4];
    const float c1 = lw + dw, c2 = rw - dw;

    float n0 = node_f(v[0], v[1], c1, c2, pw, nb);
    float n1 = node_f(v[2], v[3], c1, c2, pw, nb);
    float n2 = node_f(v[4], v[5], c1, c2, pw, nb);
    float n3 = node_f(v[6], v[7], c1, c2, pw, nb);
    float m0 = node_f(n0, n1, c1, c2, pw, nb);
    float m1 = node_f(n2, n3, c1, c2, pw, nb);
    float root = node_f(m0, m1, c1, c2, pw, nb);

    s_out[tloc * (TW + 1) + wloc] = root;
    __syncthreads();
    const int t2 = tid >> 4, w2 = tid & 15;
    float r = s_out[t2 * (TW + 1) + w2];
    __nv_bfloat16 rh = __float2bfloat16(r);
    __nv_bfloat16 rl = __float2bfloat16(r - __bfloat162float(rh));
    size_t o = (size_t)(tbase + t2) * WDIM + wbase + w2;
    g_Ah[o] = rh;
    g_Al[o] = rl;
}

// ================= K4: C = Ah*Bh + Ah*Bl + Al*Bh + bias (HMMA bf16) =====
#define BM 256
#define BN 128
#define BKK 32
// smem byte strides (padded for conflict-free ldmatrix)
#define A_RS 80      // 32 bf16 = 64B data + 16B pad
#define B_RS 272     // 128 bf16 = 256B data + 16B pad
#define A_STAGE (BM * A_RS)          // 20480
#define B_STAGE (BKK * B_RS)         // 8704
#define SM_AH 0
#define SM_AL (2 * A_STAGE)          // 40960
#define SM_BH (4 * A_STAGE)          // 81920
#define SM_BL (SM_BH + 2 * B_STAGE)  // 99328
#define SM_TOTAL (SM_BH + 4 * B_STAGE)  // 116736

__device__ __forceinline__ void cp16(uint32_t dst, const void* src) {
    asm volatile("cp.async.cg.shared.global [%0], [%1], 16;\n" :: "r"(dst), "l"(src));
}
__device__ __forceinline__ void cp_commit() {
    asm volatile("cp.async.commit_group;\n");
}
__device__ __forceinline__ void cp_wait0() {
    asm volatile("cp.async.wait_group 0;\n");
}
__device__ __forceinline__ void ldm_x4(uint32_t* r, uint32_t addr) {
    asm volatile("ldmatrix.sync.aligned.m8n8.x4.shared.b16 {%0,%1,%2,%3}, [%4];\n"
                 : "=r"(r[0]), "=r"(r[1]), "=r"(r[2]), "=r"(r[3]) : "r"(addr));
}
__device__ __forceinline__ void ldm_x4_t(uint32_t* r, uint32_t addr) {
    asm volatile("ldmatrix.sync.aligned.m8n8.x4.trans.shared.b16 {%0,%1,%2,%3}, [%4];\n"
                 : "=r"(r[0]), "=r"(r[1]), "=r"(r[2]), "=r"(r[3]) : "r"(addr));
}
__device__ __forceinline__ void mma16816(float* d, const uint32_t* a, const uint32_t* b) {
    asm volatile(
        "mma.sync.aligned.m16n8k16.row.col.f32.bf16.bf16.f32 "
        "{%0,%1,%2,%3}, {%4,%5,%6,%7}, {%8,%9}, {%0,%1,%2,%3};\n"
        : "+f"(d[0]), "+f"(d[1]), "+f"(d[2]), "+f"(d[3])
        : "r"(a[0]), "r"(a[1]), "r"(a[2]), "r"(a[3]), "r"(b[0]), "r"(b[1]));
}

__global__ __launch_bounds__(512, 1) void k_gemm(const float* __restrict__ bias,
                                                 float* __restrict__ C) {
    extern __shared__ char sm[];
    const uint32_t sbase = (uint32_t)__cvta_generic_to_shared(sm);
    const int tid = threadIdx.x;
    const int warp = tid >> 5, lane = tid & 31;
    const int wm = warp >> 2, wn = warp & 3;   // 4x4 warp grid; warp tile 64x32
    const int bm = blockIdx.y * BM, bn = blockIdx.x * BN;

    // cp.async thread mapping
    const int arow = tid >> 1;                 // 0..255
    const int ac   = (tid & 1) * 32;           // byte offset of first 16B chunk
    const int brow = tid >> 4;                 // 0..31 (k within tile)
    const int bc   = (tid & 15) * 16;          // byte offset within 256B row

    const char* gAh = (const char*)g_Ah + (size_t)(bm + arow) * (WDIM * 2);
    const char* gAl = (const char*)g_Al + (size_t)(bm + arow) * (WDIM * 2);
    const char* gBh = (const char*)g_Bh + (size_t)brow * (DDIM * 2) + (size_t)bn * 2;
    const char* gBl = (const char*)g_Bl + (size_t)brow * (DDIM * 2) + (size_t)bn * 2;

    // ldmatrix per-lane base offsets
    const uint32_t a_off = (uint32_t)((wm * 64 + (lane & 15)) * A_RS + (lane >> 4) * 16);
    const uint32_t b_off = (uint32_t)((lane & 15) * B_RS + wn * 64 + (lane >> 4) * 16);

    float d[4][4][4];
#pragma unroll
    for (int i = 0; i < 4; ++i)
#pragma unroll
        for (int j = 0; j < 4; ++j)
#pragma unroll
            for (int k = 0; k < 4; ++k) d[i][j][k] = 0.0f;

#define LOAD_STAGE(stg, kt)                                                        \
    {                                                                              \
        uint32_t sa = sbase + SM_AH + (stg) * A_STAGE + arow * A_RS + ac;          \
        const char* pA = gAh + (size_t)(kt) * 2 + ac;                              \
        cp16(sa, pA); cp16(sa + 16, pA + 16);                                      \
        uint32_t sal = sbase + SM_AL + (stg) * A_STAGE + arow * A_RS + ac;         \
        const char* pAl = gAl + (size_t)(kt) * 2 + ac;                             \
        cp16(sal, pAl); cp16(sal + 16, pAl + 16);                                  \
        uint32_t sb = sbase + SM_BH + (stg) * B_STAGE + brow * B_RS + bc;          \
        cp16(sb, gBh + (size_t)(kt) * (DDIM * 2) + bc);                            \
        uint32_t sbl = sbase + SM_BL + (stg) * B_STAGE + brow * B_RS + bc;         \
        cp16(sbl, gBl + (size_t)(kt) * (DDIM * 2) + bc);                           \
        cp_commit();                                                               \
    }

    LOAD_STAGE(0, 0);
    cp_wait0();
    __syncthreads();

    const int NT = WDIM / BKK;   // 128
    for (int t = 0; t < NT; ++t) {
        const int cur = t & 1;
        if (t + 1 < NT) LOAD_STAGE(1 - cur, (t + 1) * BKK);

        const uint32_t abase = sbase + SM_AH + cur * A_STAGE + a_off;
        const uint32_t albase = sbase + SM_AL + cur * A_STAGE + a_off;
        const uint32_t bbase = sbase + SM_BH + cur * B_STAGE + b_off;
        const uint32_t blbase = sbase + SM_BL + cur * B_STAGE + b_off;

#pragma unroll
        for (int k0 = 0; k0 < BKK; k0 += 16) {
            uint32_t bh[2][4], bl[2][4];
            ldm_x4_t(bh[0], bbase + k0 * B_RS);
            ldm_x4_t(bh[1], bbase + k0 * B_RS + 32);
            ldm_x4_t(bl[0], blbase + k0 * B_RS);
            ldm_x4_t(bl[1], blbase + k0 * B_RS + 32);
#pragma unroll
            for (int mf = 0; mf < 4; ++mf) {
                uint32_t ah[4], al[4];
                ldm_x4(ah, abase + mf * (16 * A_RS) + k0 * 2);
                ldm_x4(al, albase + mf * (16 * A_RS) + k0 * 2);
#pragma unroll
                for (int nf = 0; nf < 4; ++nf) {
                    const uint32_t* bhp = &bh[nf >> 1][(nf & 1) * 2];
                    const uint32_t* blp = &bl[nf >> 1][(nf & 1) * 2];
                    mma16816(d[mf][nf], ah, bhp);
                    mma16816(d[mf][nf], ah, blp);
                    mma16816(d[mf][nf], al, bhp);
                }
            }
        }

        if (t + 1 < NT) {
            cp_wait0();
            __syncthreads();
        }
    }

    // epilogue: bias + store
    const int row0 = bm + wm * 64 + (lane >> 2);
    const int col0 = bn + wn * 32 + (lane & 3) * 2;
#pragma unroll
    for (int nf = 0; nf < 4; ++nf) {
        const int c = col0 + nf * 8;
        float2 bb = *(const float2*)(bias + c);
#pragma unroll
        for (int mf = 0; mf < 4; ++mf) {
            const int r = row0 + mf * 16;
            float2 o0, o1;
            o0.x = d[mf][nf][0] + bb.x; o0.y = d[mf][nf][1] + bb.y;
            o1.x = d[mf][nf][2] + bb.x; o1.y = d[mf][nf][3] + bb.y;
            *(float2*)(C + (size_t)r * DDIM + c) = o0;
            *(float2*)(C + (size_t)(r + 8) * DDIM + c) = o1;
        }
    }
}

// ================= launch =================
extern "C" void kernel_launch(void* const* d_in, const int* in_sizes, int n_in,
                              void* d_out, int out_size) {
    const float* hidden      = (const float*)d_in[0];
    const float* slot_w      = (const float*)d_in[1];
    const float* slot_b      = (const float*)d_in[2];
    const float* leaf_logits = (const float*)d_in[3];
    const float* node_params = (const float*)d_in[4];
    const float* out_w       = (const float*)d_in[5];
    const float* out_b       = (const float*)d_in[6];
    float* out = (float*)d_out;
    (void)in_sizes; (void)n_in; (void)out_size;

    (void)cudaFuncSetAttribute(k_gemm, cudaFuncAttributeMaxDynamicSharedMemorySize, SM_TOTAL);

    k_selector<<<(WDIM * LEAVES + 255) / 256, 256>>>(leaf_logits);
    k_basis<<<TOKENS, 128>>>(hidden, slot_w, slot_b);
    k_split<<<(WDIM * DDIM / 4) / 256, 256>>>(out_w);
    k_tree<<<dim3(TOKENS / TT, WDIM / TW), 256>>>(node_params);
    k_gemm<<<dim3(DDIM / BN, TOKENS / BM), 512, SM_TOTAL>>>(out_b, out);
}

// round 14
// speedup vs baseline: 2.0425x; 1.2242x over previous
#include <cuda_runtime.h>
#include <cuda_bf16.h>
#include <cstdint>

// Shapes (fixed for this problem instance)
#define TOKENS 4096   // B*S = 2*2048
#define DDIM   1024   // D
#define WDIM   4096   // W
#define SLOT   8
#define CDIM   11
#define LEAVES 8      // 1 << TREE_DEPTH

// -------- scratch (device globals; no runtime allocation allowed) --------
__device__ float g_selp[WDIM * LEAVES * 12];   // [w][l][0..7]=slot weights, [8]=const bias
__device__ float g_basis[TOKENS * 12];         // [t][0..7] = tanh slots
__device__ __align__(256) __nv_bfloat16 g_Ah[(size_t)TOKENS * WDIM]; // roots hi
__device__ __align__(256) __nv_bfloat16 g_Al[(size_t)TOKENS * WDIM]; // roots lo
__device__ __align__(256) __nv_bfloat16 g_Bh[(size_t)WDIM * DDIM];   // out_w hi
__device__ __align__(256) __nv_bfloat16 g_Bl[(size_t)WDIM * DDIM];   // out_w lo

// ---------------- helpers ----------------
typedef unsigned long long u64;

__device__ __forceinline__ float tanh_exp(float x) {
    x = fminf(fmaxf(x, -15.0f), 15.0f);
    float t = __expf(2.0f * x);
    return __fdividef(t - 1.0f, t + 1.0f);
}

__device__ __forceinline__ u64 pack2(float x, float y) {
    u64 r;
    asm("mov.b64 %0, {%1, %2};" : "=l"(r) : "f"(x), "f"(y));
    return r;
}
__device__ __forceinline__ void unpack2(u64 v, float &x, float &y) {
    asm("mov.b64 {%0, %1}, %2;" : "=f"(x), "=f"(y) : "l"(v));
}
__device__ __forceinline__ u64 ffma2(u64 a, u64 b, u64 c) {
    u64 d;
    asm("fma.rn.f32x2 %0, %1, %2, %3;" : "=l"(d) : "l"(a), "l"(b), "l"(c));
    return d;
}
__device__ __forceinline__ u64 fmul2(u64 a, u64 b) {
    u64 d;
    asm("mul.rn.f32x2 %0, %1, %2;" : "=l"(d) : "l"(a), "l"(b));
    return d;
}

__device__ __forceinline__ unsigned pb2(__nv_bfloat16 a, __nv_bfloat16 b) {
    unsigned short ua = __bfloat16_as_ushort(a), ub = __bfloat16_as_ushort(b);
    return (unsigned)ua | ((unsigned)ub << 16);
}

// ================= K1: selector softmax + constant folding =================
__global__ void k_selector(const float* __restrict__ logits) {
    int idx = blockIdx.x * blockDim.x + threadIdx.x;
    if (idx >= WDIM * LEAVES) return;
    const float* row = logits + (size_t)idx * CDIM;
    float v[CDIM];
    float m = -1e30f;
#pragma unroll
    for (int c = 0; c < CDIM; ++c) { v[c] = row[c]; m = fmaxf(m, v[c]); }
    float s = 0.0f;
#pragma unroll
    for (int c = 0; c < CDIM; ++c) { v[c] = __expf(v[c] - m); s += v[c]; }
    float inv = 1.0f / s;
    float* o = g_selp + (size_t)idx * 12;
#pragma unroll
    for (int c = 0; c < SLOT; ++c) o[c] = v[c] * inv;
    o[8]  = (v[10] - v[8]) * inv;   // (-1)*sel[8] + 1*sel[10]
    o[9]  = 0.0f; o[10] = 0.0f; o[11] = 0.0f;
}

// ================= K2: slots = tanh(hidden @ slot_w + b) =================
__global__ void k_basis(const float* __restrict__ hidden,
                        const float* __restrict__ slot_w,
                        const float* __restrict__ slot_b) {
    __shared__ float red[SLOT][128];
    const int t = blockIdx.x;
    const int tid = threadIdx.x;
    float acc[SLOT];
#pragma unroll
    for (int k = 0; k < SLOT; ++k) acc[k] = 0.0f;
    const float* h = hidden + (size_t)t * DDIM;
    for (int d = tid; d < DDIM; d += 128) {
        float hv = h[d];
        const float4* wr = (const float4*)(slot_w + (size_t)d * SLOT);
        float4 w0 = wr[0], w1 = wr[1];
        acc[0] = fmaf(hv, w0.x, acc[0]); acc[1] = fmaf(hv, w0.y, acc[1]);
        acc[2] = fmaf(hv, w0.z, acc[2]); acc[3] = fmaf(hv, w0.w, acc[3]);
        acc[4] = fmaf(hv, w1.x, acc[4]); acc[5] = fmaf(hv, w1.y, acc[5]);
        acc[6] = fmaf(hv, w1.z, acc[6]); acc[7] = fmaf(hv, w1.w, acc[7]);
    }
#pragma unroll
    for (int k = 0; k < SLOT; ++k) red[k][tid] = acc[k];
    __syncthreads();
    for (int off = 64; off > 0; off >>= 1) {
        if (tid < off) {
#pragma unroll
            for (int k = 0; k < SLOT; ++k) red[k][tid] += red[k][tid + off];
        }
        __syncthreads();
    }
    if (tid < SLOT) {
        g_basis[(size_t)t * 12 + tid] = tanhf(red[tid][0] + slot_b[tid]);
    } else if (tid < 12) {
        g_basis[(size_t)t * 12 + tid] = 0.0f;
    }
}

// ================= K2b: split out_w into bf16 hi/lo =================
__global__ void k_split(const float* __restrict__ w) {
    int i = blockIdx.x * 256 + threadIdx.x;     // i indexes float4 groups
    float4 v = ((const float4*)w)[i];
    float f[4] = {v.x, v.y, v.z, v.w};
    __nv_bfloat16 h[4], l[4];
#pragma unroll
    for (int j = 0; j < 4; ++j) {
        h[j] = __float2bfloat16(f[j]);
        l[j] = __float2bfloat16(f[j] - __bfloat162float(h[j]));
    }
    uint2 ph, pl;
    ph.x = pb2(h[0], h[1]); ph.y = pb2(h[2], h[3]);
    pl.x = pb2(l[0], l[1]); pl.y = pb2(l[2], l[3]);
    ((uint2*)g_Bh)[i] = ph;
    ((uint2*)g_Bl)[i] = pl;
}

// ================= K3: fused einsum + tree -> roots =================
// Block tile: 16 tokens x 64 w. 256 threads; each thread: 1 w, 4 tokens
// (2 packed f32x2 pairs). sel coefficients packed once, reused across pairs.
#define TT 16
#define TW 64
#define SEL_WS 100   // padded per-w stride in smem floats (16B-aligned rows)

__device__ __forceinline__ u64 tanh2(u64 a) {
    float x0, x1;
    unpack2(a, x0, x1);
    return pack2(tanh_exp(x0), tanh_exp(x1));
}

__device__ __forceinline__ u64 node2(u64 L, u64 R, u64 c1P, u64 c2P, u64 pwP, u64 nbP) {
    u64 t1 = fmul2(pwP, L);
    u64 t2 = ffma2(c2P, R, nbP);
    t2 = ffma2(c1P, L, t2);
    u64 a = ffma2(t1, R, t2);
    return tanh2(a);
}

__global__ __launch_bounds__(256) void k_tree(const float* __restrict__ node_params) {
    __shared__ float s_sel[TW * SEL_WS];    // 25.6KB
    __shared__ float s_bT[SLOT * TT];       // basis transposed: [c][t]
    const int tid = threadIdx.x;
    const int tbase = blockIdx.x * TT;
    const int wbase = blockIdx.y * TW;

    // load sel tile (64 w x 96 floats) as float4; rows stay 16B-aligned
    {
        const float4* src = (const float4*)(g_selp + (size_t)wbase * 96);
        for (int i = tid; i < TW * 24; i += 256) {
            int wi = i / 24, off = i - wi * 24;
            *(float4*)&s_sel[wi * SEL_WS + off * 4] = src[wi * 24 + off];
        }
    }
    // load basis transposed: s_bT[c][t]
    if (tid < SLOT * TT) {
        int c = tid >> 4, t = tid & 15;
        s_bT[c * TT + t] = g_basis[(size_t)(tbase + t) * 12 + c];
    }
    __syncthreads();

    const int wloc = tid >> 2;   // 0..63
    const int q = tid & 3;       // token quad: tokens q*4 .. q*4+3

    // basis token-pairs: bp[c][p] = (b[c][q*4+2p], b[c][q*4+2p+1])
    u64 bp[SLOT][2];
#pragma unroll
    for (int c = 0; c < SLOT; ++c) {
        bp[c][0] = *(const u64*)&s_bT[c * TT + q * 4];
        bp[c][1] = *(const u64*)&s_bT[c * TT + q * 4 + 2];
    }

    const float* sp = s_sel + wloc * SEL_WS;
    u64 v[LEAVES][2];
#pragma unroll
    for (int l = 0; l < LEAVES; ++l) {
        float4 w0 = *(const float4*)(sp + l * 12);
        float4 w1 = *(const float4*)(sp + l * 12 + 4);
        float bias = sp[l * 12 + 8];
        u64 a0 = pack2(bias, bias), a1 = a0;
        u64 s;
        s = pack2(w0.x, w0.x); a0 = ffma2(s, bp[0][0], a0); a1 = ffma2(s, bp[0][1], a1);
        s = pack2(w0.y, w0.y); a0 = ffma2(s, bp[1][0], a0); a1 = ffma2(s, bp[1][1], a1);
        s = pack2(w0.z, w0.z); a0 = ffma2(s, bp[2][0], a0); a1 = ffma2(s, bp[2][1], a1);
        s = pack2(w0.w, w0.w); a0 = ffma2(s, bp[3][0], a0); a1 = ffma2(s, bp[3][1], a1);
        s = pack2(w1.x, w1.x); a0 = ffma2(s, bp[4][0], a0); a1 = ffma2(s, bp[4][1], a1);
        s = pack2(w1.y, w1.y); a0 = ffma2(s, bp[5][0], a0); a1 = ffma2(s, bp[5][1], a1);
        s = pack2(w1.z, w1.z); a0 = ffma2(s, bp[6][0], a0); a1 = ffma2(s, bp[6][1], a1);
        s = pack2(w1.w, w1.w); a0 = ffma2(s, bp[7][0], a0); a1 = ffma2(s, bp[7][1], a1);
        v[l][0] = a0; v[l][1] = a1;
    }

    const float lw = node_params[0], rw = node_params[1], pw = node_params[2];
    const float dw = node_params[3], nb = node_params[4];
    const float c1 = lw + dw, c2 = rw - dw;
    const u64 c1P = pack2(c1, c1), c2P = pack2(c2, c2);
    const u64 pwP = pack2(pw, pw), nbP = pack2(nb, nb);

    u64 root[2];
#pragma unroll
    for (int p = 0; p < 2; ++p) {
        u64 n0 = node2(v[0][p], v[1][p], c1P, c2P, pwP, nbP);
        u64 n1 = node2(v[2][p], v[3][p], c1P, c2P, pwP, nbP);
        u64 n2 = node2(v[4][p], v[5][p], c1P, c2P, pwP, nbP);
        u64 n3 = node2(v[6][p], v[7][p], c1P, c2P, pwP, nbP);
        u64 m0 = node2(n0, n1, c1P, c2P, pwP, nbP);
        u64 m1 = node2(n2, n3, c1P, c2P, pwP, nbP);
        root[p] = node2(m0, m1, c1P, c2P, pwP, nbP);
    }

    // store bf16 hi/lo
#pragma unroll
    for (int p = 0; p < 2; ++p) {
        float r0, r1;
        unpack2(root[p], r0, r1);
        float rr[2] = {r0, r1};
#pragma unroll
        for (int j = 0; j < 2; ++j) {
            int tok = tbase + q * 4 + p * 2 + j;
            __nv_bfloat16 rh = __float2bfloat16(rr[j]);
            __nv_bfloat16 rl = __float2bfloat16(rr[j] - __bfloat162float(rh));
            size_t o = (size_t)tok * WDIM + wbase + wloc;
            g_Ah[o] = rh;
            g_Al[o] = rl;
        }
    }
}

// ================= K4: C = Ah*Bh + Ah*Bl + Al*Bh + bias (HMMA bf16) =====
#define BM 256
#define BN 128
#define BKK 32
// smem byte strides (padded for conflict-free ldmatrix)
#define A_RS 80      // 32 bf16 = 64B data + 16B pad
#define B_RS 272     // 128 bf16 = 256B data + 16B pad
#define A_STAGE (BM * A_RS)          // 20480
#define B_STAGE (BKK * B_RS)         // 8704
#define SM_AH 0
#define SM_AL (2 * A_STAGE)          // 40960
#define SM_BH (4 * A_STAGE)          // 81920
#define SM_BL (SM_BH + 2 * B_STAGE)  // 99328
#define SM_TOTAL (SM_BH + 4 * B_STAGE)  // 116736

__device__ __forceinline__ void cp16(uint32_t dst, const void* src) {
    asm volatile("cp.async.cg.shared.global [%0], [%1], 16;\n" :: "r"(dst), "l"(src));
}
__device__ __forceinline__ void cp_commit() {
    asm volatile("cp.async.commit_group;\n");
}
__device__ __forceinline__ void cp_wait0() {
    asm volatile("cp.async.wait_group 0;\n");
}
__device__ __forceinline__ void ldm_x4(uint32_t* r, uint32_t addr) {
    asm volatile("ldmatrix.sync.aligned.m8n8.x4.shared.b16 {%0,%1,%2,%3}, [%4];\n"
                 : "=r"(r[0]), "=r"(r[1]), "=r"(r[2]), "=r"(r[3]) : "r"(addr));
}
__device__ __forceinline__ void ldm_x4_t(uint32_t* r, uint32_t addr) {
    asm volatile("ldmatrix.sync.aligned.m8n8.x4.trans.shared.b16 {%0,%1,%2,%3}, [%4];\n"
                 : "=r"(r[0]), "=r"(r[1]), "=r"(r[2]), "=r"(r[3]) : "r"(addr));
}
__device__ __forceinline__ void mma16816(float* d, const uint32_t* a, const uint32_t* b) {
    asm volatile(
        "mma.sync.aligned.m16n8k16.row.col.f32.bf16.bf16.f32 "
        "{%0,%1,%2,%3}, {%4,%5,%6,%7}, {%8,%9}, {%0,%1,%2,%3};\n"
        : "+f"(d[0]), "+f"(d[1]), "+f"(d[2]), "+f"(d[3])
        : "r"(a[0]), "r"(a[1]), "r"(a[2]), "r"(a[3]), "r"(b[0]), "r"(b[1]));
}

__global__ __launch_bounds__(512, 1) void k_gemm(const float* __restrict__ bias,
                                                 float* __restrict__ C) {
    extern __shared__ char sm[];
    const uint32_t sbase = (uint32_t)__cvta_generic_to_shared(sm);
    const int tid = threadIdx.x;
    const int warp = tid >> 5, lane = tid & 31;
    const int wm = warp >> 2, wn = warp & 3;   // 4x4 warp grid; warp tile 64x32
    const int bm = blockIdx.y * BM, bn = blockIdx.x * BN;

    // cp.async thread mapping
    const int arow = tid >> 1;                 // 0..255
    const int ac   = (tid & 1) * 32;           // byte offset of first 16B chunk
    const int brow = tid >> 4;                 // 0..31 (k within tile)
    const int bc   = (tid & 15) * 16;          // byte offset within 256B row

    const char* gAh = (const char*)g_Ah + (size_t)(bm + arow) * (WDIM * 2);
    const char* gAl = (const char*)g_Al + (size_t)(bm + arow) * (WDIM * 2);
    const char* gBh = (const char*)g_Bh + (size_t)brow * (DDIM * 2) + (size_t)bn * 2;
    const char* gBl = (const char*)g_Bl + (size_t)brow * (DDIM * 2) + (size_t)bn * 2;

    // ldmatrix per-lane base offsets
    const uint32_t a_off = (uint32_t)((wm * 64 + (lane & 15)) * A_RS + (lane >> 4) * 16);
    const uint32_t b_off = (uint32_t)((lane & 15) * B_RS + wn * 64 + (lane >> 4) * 16);

    float d[4][4][4];
#pragma unroll
    for (int i = 0; i < 4; ++i)
#pragma unroll
        for (int j = 0; j < 4; ++j)
#pragma unroll
            for (int k = 0; k < 4; ++k) d[i][j][k] = 0.0f;

#define LOAD_STAGE(stg, kt)                                                        \
    {                                                                              \
        uint32_t sa = sbase + SM_AH + (stg) * A_STAGE + arow * A_RS + ac;          \
        const char* pA = gAh + (size_t)(kt) * 2 + ac;                              \
        cp16(sa, pA); cp16(sa + 16, pA + 16);                                      \
        uint32_t sal = sbase + SM_AL + (stg) * A_STAGE + arow * A_RS + ac;         \
        const char* pAl = gAl + (size_t)(kt) * 2 + ac;                             \
        cp16(sal, pAl); cp16(sal + 16, pAl + 16);                                  \
        uint32_t sb = sbase + SM_BH + (stg) * B_STAGE + brow * B_RS + bc;          \
        cp16(sb, gBh + (size_t)(kt) * (DDIM * 2) + bc);                            \
        uint32_t sbl = sbase + SM_BL + (stg) * B_STAGE + brow * B_RS + bc;         \
        cp16(sbl, gBl + (size_t)(kt) * (DDIM * 2) + bc);                           \
        cp_commit();                                                               \
    }

    LOAD_STAGE(0, 0);
    cp_wait0();
    __syncthreads();

    const int NT = WDIM / BKK;   // 128
    for (int t = 0; t < NT; ++t) {
        const int cur = t & 1;
        if (t + 1 < NT) LOAD_STAGE(1 - cur, (t + 1) * BKK);

        const uint32_t abase = sbase + SM_AH + cur * A_STAGE + a_off;
        const uint32_t albase = sbase + SM_AL + cur * A_STAGE + a_off;
        const uint32_t bbase = sbase + SM_BH + cur * B_STAGE + b_off;
        const uint32_t blbase = sbase + SM_BL + cur * B_STAGE + b_off;

#pragma unroll
        for (int k0 = 0; k0 < BKK; k0 += 16) {
            uint32_t bh[2][4], bl[2][4];
            ldm_x4_t(bh[0], bbase + k0 * B_RS);
            ldm_x4_t(bh[1], bbase + k0 * B_RS + 32);
            ldm_x4_t(bl[0], blbase + k0 * B_RS);
            ldm_x4_t(bl[1], blbase + k0 * B_RS + 32);
#pragma unroll
            for (int mf = 0; mf < 4; ++mf) {
                uint32_t ah[4], al[4];
                ldm_x4(ah, abase + mf * (16 * A_RS) + k0 * 2);
                ldm_x4(al, albase + mf * (16 * A_RS) + k0 * 2);
#pragma unroll
                for (int nf = 0; nf < 4; ++nf) {
                    const uint32_t* bhp = &bh[nf >> 1][(nf & 1) * 2];
                    const uint32_t* blp = &bl[nf >> 1][(nf & 1) * 2];
                    mma16816(d[mf][nf], ah, bhp);
                    mma16816(d[mf][nf], ah, blp);
                    mma16816(d[mf][nf], al, bhp);
                }
            }
        }

        if (t + 1 < NT) {
            cp_wait0();
            __syncthreads();
        }
    }

    // epilogue: bias + store
    const int row0 = bm + wm * 64 + (lane >> 2);
    const int col0 = bn + wn * 32 + (lane & 3) * 2;
#pragma unroll
    for (int nf = 0; nf < 4; ++nf) {
        const int c = col0 + nf * 8;
        float2 bb = *(const float2*)(bias + c);
#pragma unroll
        for (int mf = 0; mf < 4; ++mf) {
            const int r = row0 + mf * 16;
            float2 o0, o1;
            o0.x = d[mf][nf][0] + bb.x; o0.y = d[mf][nf][1] + bb.y;
            o1.x = d[mf][nf][2] + bb.x; o1.y = d[mf][nf][3] + bb.y;
            *(float2*)(C + (size_t)r * DDIM + c) = o0;
            *(float2*)(C + (size_t)(r + 8) * DDIM + c) = o1;
        }
    }
}

// ================= launch =================
extern "C" void kernel_launch(void* const* d_in, const int* in_sizes, int n_in,
                              void* d_out, int out_size) {
    const float* hidden      = (const float*)d_in[0];
    const float* slot_w      = (const float*)d_in[1];
    const float* slot_b      = (const float*)d_in[2];
    const float* leaf_logits = (const float*)d_in[3];
    const float* node_params = (const float*)d_in[4];
    const float* out_w       = (const float*)d_in[5];
    const float* out_b       = (const float*)d_in[6];
    float* out = (float*)d_out;
    (void)in_sizes; (void)n_in; (void)out_size;

    (void)cudaFuncSetAttribute(k_gemm, cudaFuncAttributeMaxDynamicSharedMemorySize, SM_TOTAL);

    k_selector<<<(WDIM * LEAVES + 255) / 256, 256>>>(leaf_logits);
    k_basis<<<TOKENS, 128>>>(hidden, slot_w, slot_b);
    k_split<<<(WDIM * DDIM / 4) / 256, 256>>>(out_w);
    k_tree<<<dim3(TOKENS / TT, WDIM / TW), 256>>>(node_params);
    k_gemm<<<dim3(DDIM / BN, TOKENS / BM), 512, SM_TOTAL>>>(out_b, out);
}

// round 16
// speedup vs baseline: 2.7164x; 1.3299x over previous
#include <cuda_runtime.h>
#include <cuda_fp16.h>
#include <cstdint>

// Shapes (fixed for this problem instance)
#define TOKENS 4096   // B*S = 2*2048
#define DDIM   1024   // D
#define WDIM   4096   // W
#define SLOT   8
#define CDIM   11
#define LEAVES 8      // 1 << TREE_DEPTH

// -------- scratch (device globals; no runtime allocation allowed) --------
__device__ float g_selp[WDIM * LEAVES * 12];   // [w][l][0..7]=slot weights, [8]=const bias
__device__ float g_basis[TOKENS * 12];         // [t][0..7] = tanh slots
__device__ __align__(256) __half g_Ah[(size_t)TOKENS * WDIM];  // roots hi (fp16) [t][k]
__device__ __align__(256) __half g_Al[(size_t)TOKENS * WDIM];  // roots lo (fp16) [t][k]
__device__ __align__(256) __half g_Bh[(size_t)WDIM * DDIM];    // out_w fp16 [k][n]

// ---------------- helpers ----------------
typedef unsigned long long u64;

__device__ __forceinline__ float tanh_exp(float x) {
    x = fminf(fmaxf(x, -15.0f), 15.0f);
    float t = __expf(2.0f * x);
    return __fdividef(t - 1.0f, t + 1.0f);
}

__device__ __forceinline__ u64 pack2(float x, float y) {
    u64 r;
    asm("mov.b64 %0, {%1, %2};" : "=l"(r) : "f"(x), "f"(y));
    return r;
}
__device__ __forceinline__ void unpack2(u64 v, float &x, float &y) {
    asm("mov.b64 {%0, %1}, %2;" : "=f"(x), "=f"(y) : "l"(v));
}
__device__ __forceinline__ u64 ffma2(u64 a, u64 b, u64 c) {
    u64 d;
    asm("fma.rn.f32x2 %0, %1, %2, %3;" : "=l"(d) : "l"(a), "l"(b), "l"(c));
    return d;
}
__device__ __forceinline__ u64 fmul2(u64 a, u64 b) {
    u64 d;
    asm("mul.rn.f32x2 %0, %1, %2;" : "=l"(d) : "l"(a), "l"(b));
    return d;
}
__device__ __forceinline__ unsigned ph2(__half a, __half b) {
    return (unsigned)__half_as_ushort(a) | ((unsigned)__half_as_ushort(b) << 16);
}

// ================= K1: selector softmax + constant folding =================
__global__ void k_selector(const float* __restrict__ logits) {
    int idx = blockIdx.x * blockDim.x + threadIdx.x;
    if (idx >= WDIM * LEAVES) return;
    const float* row = logits + (size_t)idx * CDIM;
    float v[CDIM];
    float m = -1e30f;
#pragma unroll
    for (int c = 0; c < CDIM; ++c) { v[c] = row[c]; m = fmaxf(m, v[c]); }
    float s = 0.0f;
#pragma unroll
    for (int c = 0; c < CDIM; ++c) { v[c] = __expf(v[c] - m); s += v[c]; }
    float inv = 1.0f / s;
    float* o = g_selp + (size_t)idx * 12;
#pragma unroll
    for (int c = 0; c < SLOT; ++c) o[c] = v[c] * inv;
    o[8]  = (v[10] - v[8]) * inv;   // (-1)*sel[8] + 1*sel[10]
    o[9]  = 0.0f; o[10] = 0.0f; o[11] = 0.0f;
}

// ================= K2: slots = tanh(hidden @ slot_w + b) =================
__global__ void k_basis(const float* __restrict__ hidden,
                        const float* __restrict__ slot_w,
                        const float* __restrict__ slot_b) {
    __shared__ float red[SLOT][128];
    const int t = blockIdx.x;
    const int tid = threadIdx.x;
    float acc[SLOT];
#pragma unroll
    for (int k = 0; k < SLOT; ++k) acc[k] = 0.0f;
    const float* h = hidden + (size_t)t * DDIM;
    for (int d = tid; d < DDIM; d += 128) {
        float hv = h[d];
        const float4* wr = (const float4*)(slot_w + (size_t)d * SLOT);
        float4 w0 = wr[0], w1 = wr[1];
        acc[0] = fmaf(hv, w0.x, acc[0]); acc[1] = fmaf(hv, w0.y, acc[1]);
        acc[2] = fmaf(hv, w0.z, acc[2]); acc[3] = fmaf(hv, w0.w, acc[3]);
        acc[4] = fmaf(hv, w1.x, acc[4]); acc[5] = fmaf(hv, w1.y, acc[5]);
        acc[6] = fmaf(hv, w1.z, acc[6]); acc[7] = fmaf(hv, w1.w, acc[7]);
    }
#pragma unroll
    for (int k = 0; k < SLOT; ++k) red[k][tid] = acc[k];
    __syncthreads();
    for (int off = 64; off > 0; off >>= 1) {
        if (tid < off) {
#pragma unroll
            for (int k = 0; k < SLOT; ++k) red[k][tid] += red[k][tid + off];
        }
        __syncthreads();
    }
    if (tid < SLOT) {
        g_basis[(size_t)t * 12 + tid] = tanhf(red[tid][0] + slot_b[tid]);
    } else if (tid < 12) {
        g_basis[(size_t)t * 12 + tid] = 0.0f;
    }
}

// ================= K2b: out_w -> fp16 (single, 11-bit hi is enough) =====
__global__ void k_split(const float* __restrict__ w) {
    int i = blockIdx.x * 256 + threadIdx.x;     // float4 index
    float4 v = ((const float4*)w)[i];
    uint2 p;
    p.x = ph2(__float2half_rn(v.x), __float2half_rn(v.y));
    p.y = ph2(__float2half_rn(v.z), __float2half_rn(v.w));
    ((uint2*)g_Bh)[i] = p;
}

// ================= K3: fused einsum + tree -> roots (fp16 hi/lo) ========
#define TT 16
#define TW 64
#define SEL_WS 100

__device__ __forceinline__ u64 tanh2(u64 a) {
    float x0, x1;
    unpack2(a, x0, x1);
    return pack2(tanh_exp(x0), tanh_exp(x1));
}

__device__ __forceinline__ u64 node2(u64 L, u64 R, u64 c1P, u64 c2P, u64 pwP, u64 nbP) {
    u64 t1 = fmul2(pwP, L);
    u64 t2 = ffma2(c2P, R, nbP);
    t2 = ffma2(c1P, L, t2);
    u64 a = ffma2(t1, R, t2);
    return tanh2(a);
}

__global__ __launch_bounds__(256) void k_tree(const float* __restrict__ node_params) {
    __shared__ float s_sel[TW * SEL_WS];
    __shared__ float s_bT[SLOT * TT];
    const int tid = threadIdx.x;
    const int tbase = blockIdx.x * TT;
    const int wbase = blockIdx.y * TW;

    {
        const float4* src = (const float4*)(g_selp + (size_t)wbase * 96);
        for (int i = tid; i < TW * 24; i += 256) {
            int wi = i / 24, off = i - wi * 24;
            *(float4*)&s_sel[wi * SEL_WS + off * 4] = src[wi * 24 + off];
        }
    }
    if (tid < SLOT * TT) {
        int c = tid >> 4, t = tid & 15;
        s_bT[c * TT + t] = g_basis[(size_t)(tbase + t) * 12 + c];
    }
    __syncthreads();

    const int wloc = tid >> 2;
    const int q = tid & 3;

    u64 bp[SLOT][2];
#pragma unroll
    for (int c = 0; c < SLOT; ++c) {
        bp[c][0] = *(const u64*)&s_bT[c * TT + q * 4];
        bp[c][1] = *(const u64*)&s_bT[c * TT + q * 4 + 2];
    }

    const float* sp = s_sel + wloc * SEL_WS;
    u64 v[LEAVES][2];
#pragma unroll
    for (int l = 0; l < LEAVES; ++l) {
        float4 w0 = *(const float4*)(sp + l * 12);
        float4 w1 = *(const float4*)(sp + l * 12 + 4);
        float bias = sp[l * 12 + 8];
        u64 a0 = pack2(bias, bias), a1 = a0;
        u64 s;
        s = pack2(w0.x, w0.x); a0 = ffma2(s, bp[0][0], a0); a1 = ffma2(s, bp[0][1], a1);
        s = pack2(w0.y, w0.y); a0 = ffma2(s, bp[1][0], a0); a1 = ffma2(s, bp[1][1], a1);
        s = pack2(w0.z, w0.z); a0 = ffma2(s, bp[2][0], a0); a1 = ffma2(s, bp[2][1], a1);
        s = pack2(w0.w, w0.w); a0 = ffma2(s, bp[3][0], a0); a1 = ffma2(s, bp[3][1], a1);
        s = pack2(w1.x, w1.x); a0 = ffma2(s, bp[4][0], a0); a1 = ffma2(s, bp[4][1], a1);
        s = pack2(w1.y, w1.y); a0 = ffma2(s, bp[5][0], a0); a1 = ffma2(s, bp[5][1], a1);
        s = pack2(w1.z, w1.z); a0 = ffma2(s, bp[6][0], a0); a1 = ffma2(s, bp[6][1], a1);
        s = pack2(w1.w, w1.w); a0 = ffma2(s, bp[7][0], a0); a1 = ffma2(s, bp[7][1], a1);
        v[l][0] = a0; v[l][1] = a1;
    }

    const float lw = node_params[0], rw = node_params[1], pw = node_params[2];
    const float dw = node_params[3], nb = node_params[4];
    const float c1 = lw + dw, c2 = rw - dw;
    const u64 c1P = pack2(c1, c1), c2P = pack2(c2, c2);
    const u64 pwP = pack2(pw, pw), nbP = pack2(nb, nb);

    u64 root[2];
#pragma unroll
    for (int p = 0; p < 2; ++p) {
        u64 n0 = node2(v[0][p], v[1][p], c1P, c2P, pwP, nbP);
        u64 n1 = node2(v[2][p], v[3][p], c1P, c2P, pwP, nbP);
        u64 n2 = node2(v[4][p], v[5][p], c1P, c2P, pwP, nbP);
        u64 n3 = node2(v[6][p], v[7][p], c1P, c2P, pwP, nbP);
        u64 m0 = node2(n0, n1, c1P, c2P, pwP, nbP);
        u64 m1 = node2(n2, n3, c1P, c2P, pwP, nbP);
        root[p] = node2(m0, m1, c1P, c2P, pwP, nbP);
    }

#pragma unroll
    for (int p = 0; p < 2; ++p) {
        float r0, r1;
        unpack2(root[p], r0, r1);
        float rr[2] = {r0, r1};
#pragma unroll
        for (int j = 0; j < 2; ++j) {
            int tok = tbase + q * 4 + p * 2 + j;
            __half rh = __float2half_rn(rr[j]);
            __half rl = __float2half_rn(rr[j] - __half2float(rh));
            size_t o = (size_t)tok * WDIM + wbase + wloc;
            g_Ah[o] = rh;
            g_Al[o] = rl;
        }
    }
}

// ========== K4: C = (Ah + Al) @ Bh + bias  (fp16 HMMA, 2 terms) =========
#define BM 256
#define BN 128
#define BKK 64
// smem byte strides (padded for conflict-free ldmatrix)
#define A_RS 144     // 64 fp16 = 128B data + 16B pad (9x16B: odd stride, CF)
#define B_RS 272     // 128 fp16 = 256B data + 16B pad (17x16B: odd stride, CF)
#define A_STAGE (BM * A_RS)          // 36864
#define B_STAGE (BKK * B_RS)         // 17408
#define STG (A_STAGE + B_STAGE)      // 54272
#define SM_TOTAL (2 * STG)           // 108544

__device__ __forceinline__ void cp16(uint32_t dst, const void* src) {
    asm volatile("cp.async.cg.shared.global [%0], [%1], 16;\n" :: "r"(dst), "l"(src));
}
__device__ __forceinline__ void cp_commit() {
    asm volatile("cp.async.commit_group;\n");
}
__device__ __forceinline__ void cp_wait0() {
    asm volatile("cp.async.wait_group 0;\n");
}
__device__ __forceinline__ void ldm_x4(uint32_t* r, uint32_t addr) {
    asm volatile("ldmatrix.sync.aligned.m8n8.x4.shared.b16 {%0,%1,%2,%3}, [%4];\n"
                 : "=r"(r[0]), "=r"(r[1]), "=r"(r[2]), "=r"(r[3]) : "r"(addr));
}
__device__ __forceinline__ void ldm_x4_t(uint32_t* r, uint32_t addr) {
    asm volatile("ldmatrix.sync.aligned.m8n8.x4.trans.shared.b16 {%0,%1,%2,%3}, [%4];\n"
                 : "=r"(r[0]), "=r"(r[1]), "=r"(r[2]), "=r"(r[3]) : "r"(addr));
}
__device__ __forceinline__ void mma16816(float* d, const uint32_t* a, const uint32_t* b) {
    asm volatile(
        "mma.sync.aligned.m16n8k16.row.col.f32.f16.f16.f32 "
        "{%0,%1,%2,%3}, {%4,%5,%6,%7}, {%8,%9}, {%0,%1,%2,%3};\n"
        : "+f"(d[0]), "+f"(d[1]), "+f"(d[2]), "+f"(d[3])
        : "r"(a[0]), "r"(a[1]), "r"(a[2]), "r"(a[3]), "r"(b[0]), "r"(b[1]));
}

__global__ __launch_bounds__(512, 1) void k_gemm(const float* __restrict__ bias,
                                                 float* __restrict__ C) {
    extern __shared__ char sm[];
    const uint32_t sbase = (uint32_t)__cvta_generic_to_shared(sm);
    const int tid = threadIdx.x;
    const int warp = tid >> 5, lane = tid & 31;
    const int wm = warp >> 2, wn = warp & 3;   // 4x4 warp grid; warp tile 64x32
    const int bm = blockIdx.y * BM, bn = blockIdx.x * BN;

    // cp.async mapping: A = 256 rows x 8 chunks (16B), B = 64 rows x 16 chunks
    const int ar = tid >> 3, acg = tid & 7;          // with j: row = ar + j*64? no:
    // A: idx = j*512 + tid -> row = idx>>3 (0..255), chunk = idx&7
    // B: idx = j*512 + tid -> row = idx>>4 (0..63),  chunk = idx&15
    uint32_t a_sw[4], b_sw[2];
    uint32_t a_row[4], a_col[4];
    uint32_t b_row[2], b_col[2];
#pragma unroll
    for (int j = 0; j < 4; ++j) {
        int idx = j * 512 + tid, row = idx >> 3, c = idx & 7;
        a_sw[j] = (uint32_t)(row * A_RS + c * 16);
        a_row[j] = row; a_col[j] = c * 8;
    }
#pragma unroll
    for (int j = 0; j < 2; ++j) {
        int idx = j * 512 + tid, row = idx >> 4, c = idx & 15;
        b_sw[j] = (uint32_t)(A_STAGE + row * B_RS + c * 16);
        b_row[j] = row; b_col[j] = c * 8;
    }
    (void)ar; (void)acg;

    // ldmatrix per-lane base offsets
    const uint32_t a_off = (uint32_t)((wm * 64 + (lane & 15)) * A_RS + (lane >> 4) * 16);
    const uint32_t b_off = (uint32_t)(A_STAGE + (lane & 15) * B_RS + wn * 64 + (lane >> 4) * 16);

    float d[4][4][4];
#pragma unroll
    for (int i = 0; i < 4; ++i)
#pragma unroll
        for (int j = 0; j < 4; ++j)
#pragma unroll
            for (int k = 0; k < 4; ++k) d[i][j][k] = 0.0f;

#define LOAD_STAGE(stg, kt)                                                         \
    {                                                                               \
        const int seg = (kt) >> 12;                                                 \
        const int kl = (kt) & 4095;                                                 \
        const __half* As = seg ? g_Al : g_Ah;                                       \
        const uint32_t so = sbase + (stg) * STG;                                    \
        _Pragma("unroll")                                                           \
        for (int j = 0; j < 4; ++j)                                                 \
            cp16(so + a_sw[j], As + (size_t)(bm + a_row[j]) * WDIM + kl + a_col[j]);\
        _Pragma("unroll")                                                           \
        for (int j = 0; j < 2; ++j)                                                 \
            cp16(so + b_sw[j], g_Bh + (size_t)(kl + b_row[j]) * DDIM + bn + b_col[j]);\
        cp_commit();                                                                \
    }

    LOAD_STAGE(0, 0);
    cp_wait0();
    __syncthreads();

    const int NT = 2 * WDIM / BKK;   // 128
    for (int t = 0; t < NT; ++t) {
        const int cur = t & 1;
        if (t + 1 < NT) LOAD_STAGE(1 - cur, (t + 1) * BKK);

        const uint32_t abase = sbase + cur * STG + a_off;
        const uint32_t bbase = sbase + cur * STG + b_off;

#pragma unroll
        for (int k0 = 0; k0 < BKK; k0 += 16) {
            uint32_t bh[2][4];
            ldm_x4_t(bh[0], bbase + k0 * B_RS);
            ldm_x4_t(bh[1], bbase + k0 * B_RS + 32);
#pragma unroll
            for (int mf = 0; mf < 4; ++mf) {
                uint32_t ah[4];
                ldm_x4(ah, abase + mf * (16 * A_RS) + k0 * 2);
#pragma unroll
                for (int nf = 0; nf < 4; ++nf) {
                    mma16816(d[mf][nf], ah, &bh[nf >> 1][(nf & 1) * 2]);
                }
            }
        }

        if (t + 1 < NT) {
            cp_wait0();
            __syncthreads();
        }
    }

    // epilogue: bias + store
    const int row0 = bm + wm * 64 + (lane >> 2);
    const int col0 = bn + wn * 32 + (lane & 3) * 2;
#pragma unroll
    for (int nf = 0; nf < 4; ++nf) {
        const int c = col0 + nf * 8;
        float2 bb = *(const float2*)(bias + c);
#pragma unroll
        for (int mf = 0; mf < 4; ++mf) {
            const int r = row0 + mf * 16;
            float2 o0, o1;
            o0.x = d[mf][nf][0] + bb.x; o0.y = d[mf][nf][1] + bb.y;
            o1.x = d[mf][nf][2] + bb.x; o1.y = d[mf][nf][3] + bb.y;
            *(float2*)(C + (size_t)r * DDIM + c) = o0;
            *(float2*)(C + (size_t)(r + 8) * DDIM + c) = o1;
        }
    }
}

// ================= launch =================
extern "C" void kernel_launch(void* const* d_in, const int* in_sizes, int n_in,
                              void* d_out, int out_size) {
    const float* hidden      = (const float*)d_in[0];
    const float* slot_w      = (const float*)d_in[1];
    const float* slot_b      = (const float*)d_in[2];
    const float* leaf_logits = (const float*)d_in[3];
    const float* node_params = (const float*)d_in[4];
    const float* out_w       = (const float*)d_in[5];
    const float* out_b       = (const float*)d_in[6];
    float* out = (float*)d_out;
    (void)in_sizes; (void)n_in; (void)out_size;

    (void)cudaFuncSetAttribute(k_gemm, cudaFuncAttributeMaxDynamicSharedMemorySize, SM_TOTAL);

    k_selector<<<(WDIM * LEAVES + 255) / 256, 256>>>(leaf_logits);
    k_basis<<<TOKENS, 128>>>(hidden, slot_w, slot_b);
    k_split<<<(WDIM * DDIM / 4) / 256, 256>>>(out_w);
    k_tree<<<dim3(TOKENS / TT, WDIM / TW), 256>>>(node_params);
    k_gemm<<<dim3(DDIM / BN, TOKENS / BM), 512, SM_TOTAL>>>(out_b, out);
}

// round 17
// speedup vs baseline: 3.9980x; 1.4718x over previous
#include <cuda_runtime.h>
#include <cuda_fp16.h>
#include <cstdint>

// Shapes (fixed for this problem instance)
#define TOKENS 4096   // B*S = 2*2048
#define DDIM   1024   // D
#define WDIM   4096   // W
#define SLOT   8
#define CDIM   11
#define LEAVES 8      // 1 << TREE_DEPTH

// -------- scratch (device globals; no runtime allocation allowed) --------
__device__ float g_selp[WDIM * LEAVES * 12];   // [w][l][0..7]=slot weights, [8]=const bias
__device__ float g_basis[TOKENS * 12];         // [t][0..7] = tanh slots
__device__ __align__(256) __half g_Ah[(size_t)TOKENS * WDIM];  // roots (fp16) [t][k]
__device__ __align__(256) __half g_Bh[(size_t)WDIM * DDIM];    // out_w fp16 [k][n]

// ---------------- helpers ----------------
typedef unsigned long long u64;

__device__ __forceinline__ u64 pack2(float x, float y) {
    u64 r;
    asm("mov.b64 %0, {%1, %2};" : "=l"(r) : "f"(x), "f"(y));
    return r;
}
__device__ __forceinline__ void unpack2(u64 v, float &x, float &y) {
    asm("mov.b64 {%0, %1}, %2;" : "=f"(x), "=f"(y) : "l"(v));
}
__device__ __forceinline__ u64 ffma2(u64 a, u64 b, u64 c) {
    u64 d;
    asm("fma.rn.f32x2 %0, %1, %2, %3;" : "=l"(d) : "l"(a), "l"(b), "l"(c));
    return d;
}
__device__ __forceinline__ u64 fmul2(u64 a, u64 b) {
    u64 d;
    asm("mul.rn.f32x2 %0, %1, %2;" : "=l"(d) : "l"(a), "l"(b));
    return d;
}
__device__ __forceinline__ unsigned ph2(__half a, __half b) {
    return (unsigned)__half_as_ushort(a) | ((unsigned)__half_as_ushort(b) << 16);
}

// clamp-free tanh: 1 - 2*rcp(2^(2*log2e*x) + 1); saturates cleanly at +-inf
__device__ __forceinline__ float tanh_fast(float x) {
    float u = x * 2.8853900817779268f;   // 2*log2(e)
    float t;
    asm("ex2.approx.f32 %0, %1;" : "=f"(t) : "f"(u));
    float r;
    asm("rcp.approx.f32 %0, %1;" : "=f"(r) : "f"(t + 1.0f));
    return fmaf(-2.0f, r, 1.0f);
}

// ================= K1: selector softmax + constant folding =================
__global__ void k_selector(const float* __restrict__ logits) {
    int idx = blockIdx.x * blockDim.x + threadIdx.x;
    if (idx >= WDIM * LEAVES) return;
    const float* row = logits + (size_t)idx * CDIM;
    float v[CDIM];
    float m = -1e30f;
#pragma unroll
    for (int c = 0; c < CDIM; ++c) { v[c] = row[c]; m = fmaxf(m, v[c]); }
    float s = 0.0f;
#pragma unroll
    for (int c = 0; c < CDIM; ++c) { v[c] = __expf(v[c] - m); s += v[c]; }
    float inv = 1.0f / s;
    float* o = g_selp + (size_t)idx * 12;
#pragma unroll
    for (int c = 0; c < SLOT; ++c) o[c] = v[c] * inv;
    o[8]  = (v[10] - v[8]) * inv;   // (-1)*sel[8] + 1*sel[10]
    o[9]  = 0.0f; o[10] = 0.0f; o[11] = 0.0f;
}

// ================= K2: slots = tanh(hidden @ slot_w + b) =================
__global__ void k_basis(const float* __restrict__ hidden,
                        const float* __restrict__ slot_w,
                        const float* __restrict__ slot_b) {
    __shared__ float red[SLOT][128];
    const int t = blockIdx.x;
    const int tid = threadIdx.x;
    float acc[SLOT];
#pragma unroll
    for (int k = 0; k < SLOT; ++k) acc[k] = 0.0f;
    const float* h = hidden + (size_t)t * DDIM;
    for (int d = tid; d < DDIM; d += 128) {
        float hv = h[d];
        const float4* wr = (const float4*)(slot_w + (size_t)d * SLOT);
        float4 w0 = wr[0], w1 = wr[1];
        acc[0] = fmaf(hv, w0.x, acc[0]); acc[1] = fmaf(hv, w0.y, acc[1]);
        acc[2] = fmaf(hv, w0.z, acc[2]); acc[3] = fmaf(hv, w0.w, acc[3]);
        acc[4] = fmaf(hv, w1.x, acc[4]); acc[5] = fmaf(hv, w1.y, acc[5]);
        acc[6] = fmaf(hv, w1.z, acc[6]); acc[7] = fmaf(hv, w1.w, acc[7]);
    }
#pragma unroll
    for (int k = 0; k < SLOT; ++k) red[k][tid] = acc[k];
    __syncthreads();
    for (int off = 64; off > 0; off >>= 1) {
        if (tid < off) {
#pragma unroll
            for (int k = 0; k < SLOT; ++k) red[k][tid] += red[k][tid + off];
        }
        __syncthreads();
    }
    if (tid < SLOT) {
        g_basis[(size_t)t * 12 + tid] = tanhf(red[tid][0] + slot_b[tid]);
    } else if (tid < 12) {
        g_basis[(size_t)t * 12 + tid] = 0.0f;
    }
}

// ================= K2b: out_w -> fp16 =================
__global__ void k_split(const float* __restrict__ w) {
    int i = blockIdx.x * 256 + threadIdx.x;     // float4 index
    float4 v = ((const float4*)w)[i];
    uint2 p;
    p.x = ph2(__float2half_rn(v.x), __float2half_rn(v.y));
    p.y = ph2(__float2half_rn(v.z), __float2half_rn(v.w));
    ((uint2*)g_Bh)[i] = p;
}

// ================= K3: fused einsum + tree -> roots (fp16) ==============
#define TT 16
#define TW 64
#define SEL_WS 100

__device__ __forceinline__ u64 tanh2(u64 a) {
    float x0, x1;
    unpack2(a, x0, x1);
    return pack2(tanh_fast(x0), tanh_fast(x1));
}

__device__ __forceinline__ u64 node2(u64 L, u64 R, u64 c1P, u64 c2P, u64 pwP, u64 nbP) {
    u64 t1 = fmul2(pwP, L);
    u64 t2 = ffma2(c2P, R, nbP);
    t2 = ffma2(c1P, L, t2);
    u64 a = ffma2(t1, R, t2);
    return tanh2(a);
}

__global__ __launch_bounds__(256) void k_tree(const float* __restrict__ node_params) {
    __shared__ float s_sel[TW * SEL_WS];
    __shared__ float s_bT[SLOT * TT];
    const int tid = threadIdx.x;
    const int tbase = blockIdx.x * TT;
    const int wbase = blockIdx.y * TW;

    {
        const float4* src = (const float4*)(g_selp + (size_t)wbase * 96);
        for (int i = tid; i < TW * 24; i += 256) {
            int wi = i / 24, off = i - wi * 24;
            *(float4*)&s_sel[wi * SEL_WS + off * 4] = src[wi * 24 + off];
        }
    }
    if (tid < SLOT * TT) {
        int c = tid >> 4, t = tid & 15;
        s_bT[c * TT + t] = g_basis[(size_t)(tbase + t) * 12 + c];
    }
    __syncthreads();

    const int wloc = tid >> 2;
    const int q = tid & 3;

    u64 bp[SLOT][2];
#pragma unroll
    for (int c = 0; c < SLOT; ++c) {
        bp[c][0] = *(const u64*)&s_bT[c * TT + q * 4];
        bp[c][1] = *(const u64*)&s_bT[c * TT + q * 4 + 2];
    }

    const float* sp = s_sel + wloc * SEL_WS;
    u64 v[LEAVES][2];
#pragma unroll
    for (int l = 0; l < LEAVES; ++l) {
        float4 w0 = *(const float4*)(sp + l * 12);
        float4 w1 = *(const float4*)(sp + l * 12 + 4);
        float bias = sp[l * 12 + 8];
        u64 a0 = pack2(bias, bias), a1 = a0;
        u64 s;
        s = pack2(w0.x, w0.x); a0 = ffma2(s, bp[0][0], a0); a1 = ffma2(s, bp[0][1], a1);
        s = pack2(w0.y, w0.y); a0 = ffma2(s, bp[1][0], a0); a1 = ffma2(s, bp[1][1], a1);
        s = pack2(w0.z, w0.z); a0 = ffma2(s, bp[2][0], a0); a1 = ffma2(s, bp[2][1], a1);
        s = pack2(w0.w, w0.w); a0 = ffma2(s, bp[3][0], a0); a1 = ffma2(s, bp[3][1], a1);
        s = pack2(w1.x, w1.x); a0 = ffma2(s, bp[4][0], a0); a1 = ffma2(s, bp[4][1], a1);
        s = pack2(w1.y, w1.y); a0 = ffma2(s, bp[5][0], a0); a1 = ffma2(s, bp[5][1], a1);
        s = pack2(w1.z, w1.z); a0 = ffma2(s, bp[6][0], a0); a1 = ffma2(s, bp[6][1], a1);
        s = pack2(w1.w, w1.w); a0 = ffma2(s, bp[7][0], a0); a1 = ffma2(s, bp[7][1], a1);
        v[l][0] = a0; v[l][1] = a1;
    }

    const float lw = node_params[0], rw = node_params[1], pw = node_params[2];
    const float dw = node_params[3], nb = node_params[4];
    const float c1 = lw + dw, c2 = rw - dw;
    const u64 c1P = pack2(c1, c1), c2P = pack2(c2, c2);
    const u64 pwP = pack2(pw, pw), nbP = pack2(nb, nb);

    u64 root[2];
#pragma unroll
    for (int p = 0; p < 2; ++p) {
        u64 n0 = node2(v[0][p], v[1][p], c1P, c2P, pwP, nbP);
        u64 n1 = node2(v[2][p], v[3][p], c1P, c2P, pwP, nbP);
        u64 n2 = node2(v[4][p], v[5][p], c1P, c2P, pwP, nbP);
        u64 n3 = node2(v[6][p], v[7][p], c1P, c2P, pwP, nbP);
        u64 m0 = node2(n0, n1, c1P, c2P, pwP, nbP);
        u64 m1 = node2(n2, n3, c1P, c2P, pwP, nbP);
        root[p] = node2(m0, m1, c1P, c2P, pwP, nbP);
    }

#pragma unroll
    for (int p = 0; p < 2; ++p) {
        float r0, r1;
        unpack2(root[p], r0, r1);
        float rr[2] = {r0, r1};
#pragma unroll
        for (int j = 0; j < 2; ++j) {
            int tok = tbase + q * 4 + p * 2 + j;
            g_Ah[(size_t)tok * WDIM + wbase + wloc] = __float2half_rn(rr[j]);
        }
    }
}

// ========== K4: C = A @ Bh + bias  (fp16 HMMA, single term) =============
#define BM 256
#define BN 128
#define BKK 64
// smem byte strides (padded for conflict-free ldmatrix)
#define A_RS 144     // 64 fp16 = 128B data + 16B pad
#define B_RS 272     // 128 fp16 = 256B data + 16B pad
#define A_STAGE (BM * A_RS)          // 36864
#define B_STAGE (BKK * B_RS)         // 17408
#define STG (A_STAGE + B_STAGE)      // 54272
#define SM_TOTAL (2 * STG)           // 108544

__device__ __forceinline__ void cp16(uint32_t dst, const void* src) {
    asm volatile("cp.async.cg.shared.global [%0], [%1], 16;\n" :: "r"(dst), "l"(src));
}
__device__ __forceinline__ void cp_commit() {
    asm volatile("cp.async.commit_group;\n");
}
__device__ __forceinline__ void cp_wait0() {
    asm volatile("cp.async.wait_group 0;\n");
}
__device__ __forceinline__ void ldm_x4(uint32_t* r, uint32_t addr) {
    asm volatile("ldmatrix.sync.aligned.m8n8.x4.shared.b16 {%0,%1,%2,%3}, [%4];\n"
                 : "=r"(r[0]), "=r"(r[1]), "=r"(r[2]), "=r"(r[3]) : "r"(addr));
}
__device__ __forceinline__ void ldm_x4_t(uint32_t* r, uint32_t addr) {
    asm volatile("ldmatrix.sync.aligned.m8n8.x4.trans.shared.b16 {%0,%1,%2,%3}, [%4];\n"
                 : "=r"(r[0]), "=r"(r[1]), "=r"(r[2]), "=r"(r[3]) : "r"(addr));
}
__device__ __forceinline__ void mma16816(float* d, const uint32_t* a, const uint32_t* b) {
    asm volatile(
        "mma.sync.aligned.m16n8k16.row.col.f32.f16.f16.f32 "
        "{%0,%1,%2,%3}, {%4,%5,%6,%7}, {%8,%9}, {%0,%1,%2,%3};\n"
        : "+f"(d[0]), "+f"(d[1]), "+f"(d[2]), "+f"(d[3])
        : "r"(a[0]), "r"(a[1]), "r"(a[2]), "r"(a[3]), "r"(b[0]), "r"(b[1]));
}

__global__ __launch_bounds__(512, 1) void k_gemm(const float* __restrict__ bias,
                                                 float* __restrict__ C) {
    extern __shared__ char sm[];
    const uint32_t sbase = (uint32_t)__cvta_generic_to_shared(sm);
    const int tid = threadIdx.x;
    const int warp = tid >> 5, lane = tid & 31;
    const int wm = warp >> 2, wn = warp & 3;   // 4x4 warp grid; warp tile 64x32
    const int bm = blockIdx.y * BM, bn = blockIdx.x * BN;

    // cp.async mapping: A = 256 rows x 8 chunks (16B), B = 64 rows x 16 chunks
    uint32_t a_sw[4], b_sw[2];
    uint32_t a_row[4], a_col[4];
    uint32_t b_row[2], b_col[2];
#pragma unroll
    for (int j = 0; j < 4; ++j) {
        int idx = j * 512 + tid, row = idx >> 3, c = idx & 7;
        a_sw[j] = (uint32_t)(row * A_RS + c * 16);
        a_row[j] = row; a_col[j] = c * 8;
    }
#pragma unroll
    for (int j = 0; j < 2; ++j) {
        int idx = j * 512 + tid, row = idx >> 4, c = idx & 15;
        b_sw[j] = (uint32_t)(A_STAGE + row * B_RS + c * 16);
        b_row[j] = row; b_col[j] = c * 8;
    }

    // ldmatrix per-lane base offsets
    const uint32_t a_off = (uint32_t)((wm * 64 + (lane & 15)) * A_RS + (lane >> 4) * 16);
    const uint32_t b_off = (uint32_t)(A_STAGE + (lane & 15) * B_RS + wn * 64 + (lane >> 4) * 16);

    float d[4][4][4];
#pragma unroll
    for (int i = 0; i < 4; ++i)
#pragma unroll
        for (int j = 0; j < 4; ++j)
#pragma unroll
            for (int k = 0; k < 4; ++k) d[i][j][k] = 0.0f;

#define LOAD_STAGE(stg, kt)                                                           \
    {                                                                                 \
        const uint32_t so = sbase + (stg) * STG;                                      \
        _Pragma("unroll")                                                             \
        for (int j = 0; j < 4; ++j)                                                   \
            cp16(so + a_sw[j], g_Ah + (size_t)(bm + a_row[j]) * WDIM + (kt) + a_col[j]); \
        _Pragma("unroll")                                                             \
        for (int j = 0; j < 2; ++j)                                                   \
            cp16(so + b_sw[j], g_Bh + (size_t)((kt) + b_row[j]) * DDIM + bn + b_col[j]); \
        cp_commit();                                                                  \
    }

    LOAD_STAGE(0, 0);
    cp_wait0();
    __syncthreads();

    const int NT = WDIM / BKK;   // 64
    for (int t = 0; t < NT; ++t) {
        const int cur = t & 1;
        if (t + 1 < NT) LOAD_STAGE(1 - cur, (t + 1) * BKK);

        const uint32_t abase = sbase + cur * STG + a_off;
        const uint32_t bbase = sbase + cur * STG + b_off;

#pragma unroll
        for (int k0 = 0; k0 < BKK; k0 += 16) {
            uint32_t bh[2][4];
            ldm_x4_t(bh[0], bbase + k0 * B_RS);
            ldm_x4_t(bh[1], bbase + k0 * B_RS + 32);
#pragma unroll
            for (int mf = 0; mf < 4; ++mf) {
                uint32_t ah[4];
                ldm_x4(ah, abase + mf * (16 * A_RS) + k0 * 2);
#pragma unroll
                for (int nf = 0; nf < 4; ++nf) {
                    mma16816(d[mf][nf], ah, &bh[nf >> 1][(nf & 1) * 2]);
                }
            }
        }

        if (t + 1 < NT) {
            cp_wait0();
            __syncthreads();
        }
    }

    // epilogue: bias + store
    const int row0 = bm + wm * 64 + (lane >> 2);
    const int col0 = bn + wn * 32 + (lane & 3) * 2;
#pragma unroll
    for (int nf = 0; nf < 4; ++nf) {
        const int c = col0 + nf * 8;
        float2 bb = *(const float2*)(bias + c);
#pragma unroll
        for (int mf = 0; mf < 4; ++mf) {
            const int r = row0 + mf * 16;
            float2 o0, o1;
            o0.x = d[mf][nf][0] + bb.x; o0.y = d[mf][nf][1] + bb.y;
            o1.x = d[mf][nf][2] + bb.x; o1.y = d[mf][nf][3] + bb.y;
            *(float2*)(C + (size_t)r * DDIM + c) = o0;
            *(float2*)(C + (size_t)(r + 8) * DDIM + c) = o1;
        }
    }
}

// ================= launch =================
extern "C" void kernel_launch(void* const* d_in, const int* in_sizes, int n_in,
                              void* d_out, int out_size) {
    const float* hidden      = (const float*)d_in[0];
    const float* slot_w      = (const float*)d_in[1];
    const float* slot_b      = (const float*)d_in[2];
    const float* leaf_logits = (const float*)d_in[3];
    const float* node_params = (const float*)d_in[4];
    const float* out_w       = (const float*)d_in[5];
    const float* out_b       = (const float*)d_in[6];
    float* out = (float*)d_out;
    (void)in_sizes; (void)n_in; (void)out_size;

    (void)cudaFuncSetAttribute(k_gemm, cudaFuncAttributeMaxDynamicSharedMemorySize, SM_TOTAL);

    k_selector<<<(WDIM * LEAVES + 255) / 256, 256>>>(leaf_logits);
    k_basis<<<TOKENS, 128>>>(hidden, slot_w, slot_b);
    k_split<<<(WDIM * DDIM / 4) / 256, 256>>>(out_w);
    k_tree<<<dim3(TOKENS / TT, WDIM / TW), 256>>>(node_params);
    k_gemm<<<dim3(DDIM / BN, TOKENS / BM), 512, SM_TOTAL>>>(out_b, out);
}